// round 1
// baseline (speedup 1.0000x reference)
#include <cuda_runtime.h>
#include <math.h>
#include <stdint.h>

#define N_NODES 50000
#define E_EDGES 200000
#define TOT_E   250000   // edges + self loops
#define HID     64
#define XD      512      // [xl | xr] width = 2 * HEADS*HID
#define T_STEPS 3

// ---------------- scratch (__device__ globals; no cudaMalloc allowed) -------
__device__ int   g_cnt[N_NODES + 1];     // counts -> inclusive scan (CSR offsets)
__device__ int   g_cur[N_NODES];         // fill cursors
__device__ int   g_srcs[TOT_E];          // CSR: src node per incoming edge
__device__ float g_h0[N_NODES * HID];
__device__ float g_h[N_NODES * HID];
__device__ float g_base[(size_t)N_NODES * XD];   // h0 @ Wc2 + [bl|br]
__device__ float g_xlr[(size_t)N_NODES * XD];    // h  @ Wc1 + base  => [xl|xr]
__device__ float g_Wc1[HID * XD];
__device__ float g_Wc2[HID * XD];
__device__ float g_biasC[XD];

// ---------------- CSR construction -----------------------------------------
__global__ void k_init_cnt() {
    int i = blockIdx.x * blockDim.x + threadIdx.x;
    if (i < N_NODES) g_cnt[i] = 1;   // self loop
}

__global__ void k_count(const int* __restrict__ ei) {
    int e = blockIdx.x * blockDim.x + threadIdx.x;
    if (e < E_EDGES) atomicAdd(&g_cnt[ei[E_EDGES + e]], 1);
}

// single-block inclusive scan over g_cnt[0..N_NODES)
__global__ void k_scan() {
    __shared__ int wsum[32];
    int tid = threadIdx.x, lane = tid & 31, wid = tid >> 5;
    int carry = 0;
    for (int base = 0; base < N_NODES; base += 1024) {
        int i = base + tid;
        int v = (i < N_NODES) ? g_cnt[i] : 0;
        int sv = v;
#pragma unroll
        for (int d = 1; d < 32; d <<= 1) {
            int u = __shfl_up_sync(0xffffffffu, sv, d);
            if (lane >= d) sv += u;
        }
        if (lane == 31) wsum[wid] = sv;
        __syncthreads();
        if (wid == 0) {
            int w = wsum[lane];
#pragma unroll
            for (int d = 1; d < 32; d <<= 1) {
                int u = __shfl_up_sync(0xffffffffu, w, d);
                if (lane >= d) w += u;
            }
            wsum[lane] = w;
        }
        __syncthreads();
        int add = (wid > 0) ? wsum[wid - 1] : 0;
        if (i < N_NODES) g_cnt[i] = sv + add + carry;
        int total = wsum[31];
        __syncthreads();
        carry += total;
    }
}

__global__ void k_selfloop_cursor() {
    int n = blockIdx.x * blockDim.x + threadIdx.x;
    if (n >= N_NODES) return;
    int beg = (n == 0) ? 0 : g_cnt[n - 1];
    g_srcs[beg] = n;         // self loop first
    g_cur[n] = beg + 1;
}

__global__ void k_fill(const int* __restrict__ ei) {
    int e = blockIdx.x * blockDim.x + threadIdx.x;
    if (e >= E_EDGES) return;
    int d = ei[E_EDGES + e];
    int p = atomicAdd(&g_cur[d], 1);
    g_srcs[p] = ei[e];
}

// ---------------- weight prep: Wc1 = top64 rows of [Wl|Wr], Wc2 = bottom ----
__global__ void k_prepw(const float* __restrict__ Wl, const float* __restrict__ Wr,
                        const float* __restrict__ bl, const float* __restrict__ br) {
    int idx = blockIdx.x * blockDim.x + threadIdx.x;  // 64*512
    if (idx >= HID * XD) return;
    int k = idx >> 9;        // /512
    int j = idx & 511;
    float vt, vb;
    if (j < 256) { vt = Wl[k * 256 + j];        vb = Wl[(k + 64) * 256 + j]; }
    else         { vt = Wr[k * 256 + (j-256)];  vb = Wr[(k + 64) * 256 + (j-256)]; }
    g_Wc1[idx] = vt;
    g_Wc2[idx] = vb;
    if (idx < XD) g_biasC[idx] = (idx < 256) ? bl[idx] : br[idx - 256];
}

// ---------------- h0 = feat @ W_in + b_in ; h = h0 --------------------------
__global__ void k_h0(const float* __restrict__ feat, const float* __restrict__ W_in,
                     const float* __restrict__ b_in) {
    __shared__ float Ws[32 * 64];
    __shared__ float fs[4][32];
    int tid = threadIdx.x;
    for (int i = tid; i < 32 * 64; i += 256) Ws[i] = W_in[i];
    if (tid < 128) {
        int r = blockIdx.x * 4 + (tid >> 5);
        fs[tid >> 5][tid & 31] = (r < N_NODES) ? feat[r * 32 + (tid & 31)] : 0.f;
    }
    __syncthreads();
    int ty = tid >> 6;          // 0..3 local row
    int c = tid & 63;
    int r = blockIdx.x * 4 + ty;
    if (r >= N_NODES) return;
    float s = b_in[c];
#pragma unroll
    for (int k = 0; k < 32; k++) s += fs[ty][k] * Ws[k * 64 + c];
    g_h0[r * 64 + c] = s;
    g_h[r * 64 + c] = s;
}

// ---------------- main GEMM: C[N,512] = A[N,64] @ W[64,512] + addend --------
// addend_is_bias: addend is a 512-vector (row broadcast); else full [N,512].
__global__ void k_gemm(const float* __restrict__ A, const float* __restrict__ W,
                       const float* __restrict__ addend, int addend_is_bias,
                       float* __restrict__ C) {
    __shared__ float As[64 * 68];
    __shared__ float Bs[64 * 68];
    int tid = threadIdx.x;
    int row0 = blockIdx.x * 64;
    int colB = blockIdx.y * 64;
    for (int i = tid; i < 64 * 64; i += 256) {
        int m = i >> 6, k = i & 63;
        int r = row0 + m;
        As[m * 68 + k] = (r < N_NODES) ? A[r * 64 + k] : 0.f;
    }
    for (int i = tid; i < 64 * 64; i += 256) {
        int k = i >> 6, c = i & 63;
        Bs[k * 68 + c] = W[k * 512 + colB + c];
    }
    __syncthreads();

    int r0 = (tid >> 4) * 4;
    int c0 = (tid & 15) * 4;
    unsigned long long acc[4][2];
#pragma unroll
    for (int i = 0; i < 4; i++) { acc[i][0] = 0ull; acc[i][1] = 0ull; }

#pragma unroll 4
    for (int k = 0; k < 64; k++) {
        unsigned long long b01 = *(const unsigned long long*)&Bs[k * 68 + c0];
        unsigned long long b23 = *(const unsigned long long*)&Bs[k * 68 + c0 + 2];
#pragma unroll
        for (int i = 0; i < 4; i++) {
            float a = As[(r0 + i) * 68 + k];
            unsigned long long aa;
            asm("mov.b64 %0, {%1, %1};" : "=l"(aa) : "r"(__float_as_uint(a)));
            asm("fma.rn.f32x2 %0, %1, %2, %0;" : "+l"(acc[i][0]) : "l"(aa), "l"(b01));
            asm("fma.rn.f32x2 %0, %1, %2, %0;" : "+l"(acc[i][1]) : "l"(aa), "l"(b23));
        }
    }

#pragma unroll
    for (int i = 0; i < 4; i++) {
        int r = row0 + r0 + i;
        if (r >= N_NODES) continue;
        unsigned int u0, u1, u2, u3;
        asm("mov.b64 {%0, %1}, %2;" : "=r"(u0), "=r"(u1) : "l"(acc[i][0]));
        asm("mov.b64 {%0, %1}, %2;" : "=r"(u2), "=r"(u3) : "l"(acc[i][1]));
        float4 v;
        v.x = __uint_as_float(u0); v.y = __uint_as_float(u1);
        v.z = __uint_as_float(u2); v.w = __uint_as_float(u3);
        int cg = colB + c0;
        if (addend_is_bias) {
            v.x += addend[cg]; v.y += addend[cg + 1];
            v.z += addend[cg + 2]; v.w += addend[cg + 3];
        } else {
            const float4 b = *(const float4*)&addend[(size_t)r * XD + cg];
            v.x += b.x; v.y += b.y; v.z += b.z; v.w += b.w;
        }
        *(float4*)&C[(size_t)r * XD + cg] = v;
    }
}

// ---------------- edge kernel: one warp per dst node ------------------------
// layout: lane holds j = lane*8 .. lane*8+7; head = lane>>3; channel c = (lane&7)*8+i
__global__ void k_edge(const int* __restrict__ node_mask,
                       const float* __restrict__ att,
                       const float* __restrict__ b_conv, int t) {
    int gw = (blockIdx.x * blockDim.x + threadIdx.x) >> 5;
    int lane = threadIdx.x & 31;
    if (gw >= N_NODES) return;
    int n = gw;
    if (node_mask[n] <= t) return;

    int j0 = lane * 8;
    const float4 at0 = *(const float4*)&att[j0];
    const float4 at1 = *(const float4*)&att[j0 + 4];
    const float* xrp = &g_xlr[(size_t)n * XD + 256 + j0];
    const float4 xr0 = *(const float4*)xrp;
    const float4 xr1 = *(const float4*)(xrp + 4);

    float acc[8];
#pragma unroll
    for (int i = 0; i < 8; i++) acc[i] = 0.f;
    float den = 0.f;

    int beg = (n == 0) ? 0 : g_cnt[n - 1];
    int end = g_cnt[n];
    for (int e = beg; e < end; e++) {
        int s = g_srcs[e];
        if (node_mask[s] <= t) continue;
        const float* xp = &g_xlr[(size_t)s * XD + j0];
        const float4 x0 = *(const float4*)xp;
        const float4 x1 = *(const float4*)(xp + 4);
        // leaky_relu(xl + xr) dot att  (partial over this lane's 8 channels)
        float p;
        {
            float v;
            v = x0.x + xr0.x; v = v > 0.f ? v : 0.2f * v; p  = v * at0.x;
            v = x0.y + xr0.y; v = v > 0.f ? v : 0.2f * v; p += v * at0.y;
            v = x0.z + xr0.z; v = v > 0.f ? v : 0.2f * v; p += v * at0.z;
            v = x0.w + xr0.w; v = v > 0.f ? v : 0.2f * v; p += v * at0.w;
            v = x1.x + xr1.x; v = v > 0.f ? v : 0.2f * v; p += v * at1.x;
            v = x1.y + xr1.y; v = v > 0.f ? v : 0.2f * v; p += v * at1.y;
            v = x1.z + xr1.z; v = v > 0.f ? v : 0.2f * v; p += v * at1.z;
            v = x1.w + xr1.w; v = v > 0.f ? v : 0.2f * v; p += v * at1.w;
        }
        // reduce across the 8 lanes of this head
        p += __shfl_xor_sync(0xffffffffu, p, 1);
        p += __shfl_xor_sync(0xffffffffu, p, 2);
        p += __shfl_xor_sync(0xffffffffu, p, 4);
        float ex = __expf(p);     // softmax shift-invariant; scores are O(1)
        den += ex;
        acc[0] += ex * x0.x; acc[1] += ex * x0.y;
        acc[2] += ex * x0.z; acc[3] += ex * x0.w;
        acc[4] += ex * x1.x; acc[5] += ex * x1.y;
        acc[6] += ex * x1.z; acc[7] += ex * x1.w;
    }

    float rden = 1.f / fmaxf(den, 1e-16f);
    float vres[8];
#pragma unroll
    for (int i = 0; i < 8; i++) {
        float v = acc[i] * rden;
        v += __shfl_xor_sync(0xffffffffu, v, 8);    // sum heads
        v += __shfl_xor_sync(0xffffffffu, v, 16);
        vres[i] = v;
    }
    if (lane < 8) {
#pragma unroll
        for (int i = 0; i < 8; i++) {
            int c = lane * 8 + i;
            float bias = b_conv[c] + b_conv[64 + c] + b_conv[128 + c] + b_conv[192 + c];
            g_h[n * 64 + c] = tanhf(vres[i] + bias);
        }
    }
}

// ---------------- out = (h @ Wg + bg) * (current_state > 0) -----------------
__global__ void k_out(const float* __restrict__ Wg, const float* __restrict__ bg,
                      const int* __restrict__ cs, float* __restrict__ out) {
    __shared__ float Ws[64 * 32];
    __shared__ float hs[8][64];
    int tid = threadIdx.x;
    for (int i = tid; i < 64 * 32; i += 256) Ws[i] = Wg[i];
    for (int i = tid; i < 8 * 64; i += 256) {
        int r = blockIdx.x * 8 + (i >> 6);
        hs[i >> 6][i & 63] = (r < N_NODES) ? g_h[r * 64 + (i & 63)] : 0.f;
    }
    __syncthreads();
    int ty = tid >> 5;
    int c = tid & 31;
    int r = blockIdx.x * 8 + ty;
    if (r >= N_NODES) return;
    float s = bg[c];
#pragma unroll
    for (int k = 0; k < 64; k++) s += hs[ty][k] * Ws[k * 32 + c];
    out[r * 32 + c] = (cs[r] > 0) ? s : 0.f;
}

// ---------------- launch -----------------------------------------------------
extern "C" void kernel_launch(void* const* d_in, const int* in_sizes, int n_in,
                              void* d_out, int out_size) {
    const float* feat  = (const float*)d_in[0];
    const float* W_in  = (const float*)d_in[1];
    const float* b_in  = (const float*)d_in[2];
    const float* Wl    = (const float*)d_in[3];
    const float* bl    = (const float*)d_in[4];
    const float* Wr    = (const float*)d_in[5];
    const float* br    = (const float*)d_in[6];
    const float* att   = (const float*)d_in[7];
    const float* bconv = (const float*)d_in[8];
    const float* Wg    = (const float*)d_in[9];
    const float* bg    = (const float*)d_in[10];
    const int*   ei    = (const int*)d_in[11];
    const int*   mask  = (const int*)d_in[12];
    const int*   cstat = (const int*)d_in[13];
    float* out = (float*)d_out;

    float *p_h0, *p_h, *p_base, *p_xlr, *p_Wc1, *p_Wc2, *p_biasC;
    cudaGetSymbolAddress((void**)&p_h0, g_h0);
    cudaGetSymbolAddress((void**)&p_h, g_h);
    cudaGetSymbolAddress((void**)&p_base, g_base);
    cudaGetSymbolAddress((void**)&p_xlr, g_xlr);
    cudaGetSymbolAddress((void**)&p_Wc1, g_Wc1);
    cudaGetSymbolAddress((void**)&p_Wc2, g_Wc2);
    cudaGetSymbolAddress((void**)&p_biasC, g_biasC);

    // CSR build
    k_init_cnt<<<(N_NODES + 255) / 256, 256>>>();
    k_count<<<(E_EDGES + 255) / 256, 256>>>(ei);
    k_scan<<<1, 1024>>>();
    k_selfloop_cursor<<<(N_NODES + 255) / 256, 256>>>();
    k_fill<<<(E_EDGES + 255) / 256, 256>>>(ei);

    // weights + invariants
    k_prepw<<<(HID * XD + 255) / 256, 256>>>(Wl, Wr, bl, br);
    k_h0<<<(N_NODES + 3) / 4, 256>>>(feat, W_in, b_in);

    dim3 gg((N_NODES + 63) / 64, XD / 64);
    k_gemm<<<gg, 256>>>(p_h0, p_Wc2, p_biasC, 1, p_base);   // base = h0@Wc2 + [bl|br]

    for (int t = 0; t < T_STEPS; t++) {
        k_gemm<<<gg, 256>>>(p_h, p_Wc1, p_base, 0, p_xlr);  // xlr = h@Wc1 + base
        k_edge<<<(N_NODES * 32 + 255) / 256, 256>>>(mask, att, bconv, t);
    }

    k_out<<<(N_NODES + 7) / 8, 256>>>(Wg, bg, cstat, out);
}

// round 2
// speedup vs baseline: 2.1373x; 2.1373x over previous
#include <cuda_runtime.h>
#include <math.h>
#include <stdint.h>

#define N_NODES 50000
#define E_EDGES 200000
#define TOT_E   250000
#define HID     64
#define XD      512
#define T_STEPS 3

// ---------------- device scratch --------------------------------------------
__device__ int   g_cnt[N_NODES + 1];
__device__ int   g_cur[N_NODES];
__device__ int   g_srcs[TOT_E];
__device__ int   g_order[N_NODES];    // nodes sorted by mask descending
__device__ int   g_hist[4];
__device__ int   g_bcur[4];
__device__ int   g_nact[4];           // n_act[t] = #nodes with mask > t
__device__ float g_h0[N_NODES * HID];
__device__ float g_h[N_NODES * HID];
__device__ float g_base[(size_t)N_NODES * XD];
__device__ float g_xlr[(size_t)N_NODES * XD];
__device__ float g_Wc1[HID * XD];
__device__ float g_Wc2[HID * XD];
__device__ float g_biasC[XD];
__device__ float g_bias2[HID];        // sum over heads of b_conv

// ---------------- prep ------------------------------------------------------
__global__ void k_zero() {
    int i = blockIdx.x * blockDim.x + threadIdx.x;
    if (i < N_NODES) g_cnt[i] = 1;      // self loop
    if (i < 4) { g_hist[i] = 0; g_bcur[i] = 0; }
}

__global__ void k_hist(const int* __restrict__ mask) {
    __shared__ int sh[4];
    if (threadIdx.x < 4) sh[threadIdx.x] = 0;
    __syncthreads();
    int i = blockIdx.x * blockDim.x + threadIdx.x;
    if (i < N_NODES) {
        int m = mask[i]; m = m < 0 ? 0 : (m > 3 ? 3 : m);
        atomicAdd(&sh[m], 1);
    }
    __syncthreads();
    if (threadIdx.x < 4) atomicAdd(&g_hist[threadIdx.x], sh[threadIdx.x]);
}

__global__ void k_count(const int* __restrict__ ei) {
    int e = blockIdx.x * blockDim.x + threadIdx.x;
    if (e < E_EDGES) atomicAdd(&g_cnt[ei[E_EDGES + e]], 1);
}

// single-block inclusive scan over g_cnt
__global__ void k_scan() {
    __shared__ int wsum[32];
    int tid = threadIdx.x, lane = tid & 31, wid = tid >> 5;
    int carry = 0;
    for (int base = 0; base < N_NODES; base += 1024) {
        int i = base + tid;
        int v = (i < N_NODES) ? g_cnt[i] : 0;
        int sv = v;
#pragma unroll
        for (int d = 1; d < 32; d <<= 1) {
            int u = __shfl_up_sync(0xffffffffu, sv, d);
            if (lane >= d) sv += u;
        }
        if (lane == 31) wsum[wid] = sv;
        __syncthreads();
        if (wid == 0) {
            int w = wsum[lane];
#pragma unroll
            for (int d = 1; d < 32; d <<= 1) {
                int u = __shfl_up_sync(0xffffffffu, w, d);
                if (lane >= d) w += u;
            }
            wsum[lane] = w;
        }
        __syncthreads();
        int add = (wid > 0) ? wsum[wid - 1] : 0;
        if (i < N_NODES) g_cnt[i] = sv + add + carry;
        int total = wsum[31];
        __syncthreads();
        carry += total;
    }
}

// selfloop + cursors + bucket scatter (needs g_cnt scanned, g_hist final)
__global__ void k_scatter(const int* __restrict__ mask) {
    __shared__ int scnt[4], sbase[4];
    int tid = threadIdx.x;
    if (tid < 4) scnt[tid] = 0;
    __syncthreads();
    int i = blockIdx.x * blockDim.x + tid;
    int m = 0, loc = 0;
    if (i < N_NODES) {
        int beg = (i == 0) ? 0 : g_cnt[i - 1];
        g_srcs[beg] = i;
        g_cur[i] = beg + 1;
        m = mask[i]; m = m < 0 ? 0 : (m > 3 ? 3 : m);
        loc = atomicAdd(&scnt[m], 1);
    }
    __syncthreads();
    if (tid < 4) sbase[tid] = atomicAdd(&g_bcur[tid], scnt[tid]);
    __syncthreads();
    if (i < N_NODES) {
        int h1 = g_hist[1], h2 = g_hist[2], h3 = g_hist[3];
        int start = (m == 3) ? 0 : ((m == 2) ? h3 : ((m == 1) ? h3 + h2 : h3 + h2 + h1));
        g_order[start + sbase[m] + loc] = i;
        if (i == 0) {
            g_nact[0] = h1 + h2 + h3;
            g_nact[1] = h2 + h3;
            g_nact[2] = h3;
            g_nact[3] = 0;
        }
    }
}

__global__ void k_fill(const int* __restrict__ ei) {
    int e = blockIdx.x * blockDim.x + threadIdx.x;
    if (e >= E_EDGES) return;
    int d = ei[E_EDGES + e];
    int p = atomicAdd(&g_cur[d], 1);
    g_srcs[p] = ei[e];
}

// ---------------- weight prep -----------------------------------------------
__global__ void k_prepw(const float* __restrict__ Wl, const float* __restrict__ Wr,
                        const float* __restrict__ bl, const float* __restrict__ br,
                        const float* __restrict__ bconv) {
    int idx = blockIdx.x * blockDim.x + threadIdx.x;
    if (idx >= HID * XD) return;
    int k = idx >> 9;
    int j = idx & 511;
    float vt, vb;
    if (j < 256) { vt = Wl[k * 256 + j];         vb = Wl[(k + 64) * 256 + j]; }
    else         { vt = Wr[k * 256 + (j - 256)]; vb = Wr[(k + 64) * 256 + (j - 256)]; }
    g_Wc1[idx] = vt;
    g_Wc2[idx] = vb;
    if (idx < XD) g_biasC[idx] = (idx < 256) ? bl[idx] : br[idx - 256];
    if (idx < HID) g_bias2[idx] = bconv[idx] + bconv[64 + idx] + bconv[128 + idx] + bconv[192 + idx];
}

// ---------------- h0 = feat @ W_in + b_in -----------------------------------
__global__ void k_h0(const float* __restrict__ feat, const float* __restrict__ W_in,
                     const float* __restrict__ b_in) {
    __shared__ float Ws[32 * 64];
    __shared__ float fs[4][32];
    int tid = threadIdx.x;
    for (int i = tid; i < 32 * 64; i += 256) Ws[i] = W_in[i];
    if (tid < 128) {
        int r = blockIdx.x * 4 + (tid >> 5);
        fs[tid >> 5][tid & 31] = (r < N_NODES) ? feat[r * 32 + (tid & 31)] : 0.f;
    }
    __syncthreads();
    int ty = tid >> 6;
    int c = tid & 63;
    int r = blockIdx.x * 4 + ty;
    if (r >= N_NODES) return;
    float s = b_in[c];
#pragma unroll
    for (int k = 0; k < 32; k++) s += fs[ty][k] * Ws[k * 64 + c];
    g_h0[r * 64 + c] = s;
    g_h[r * 64 + c] = s;
}

// ---------------- compacted GEMM: C[ord[r],512] = A[ord[r],64]@W + addend ---
// Block: 64 rows x 128 cols, 128 threads, thread = 8 rows x 8 cols
// (4 col-pairs at stride 32 => every B LDS.64 is one contiguous 128B warp read)
__global__ __launch_bounds__(128, 4) void k_gemm(
    const float* __restrict__ A, const float* __restrict__ W,
    const float* __restrict__ addend, int addend_is_bias,
    int tsel, float* __restrict__ C)
{
    extern __shared__ float sm[];
    float* As = sm;              // [64][65]
    float* Bs = sm + 64 * 65;    // [64][128]
    int nact = g_nact[tsel];
    int row0 = blockIdx.x * 64;
    if (row0 >= nact) return;
    int colB = blockIdx.y * 128;
    int tid = threadIdx.x;
    int nrow = nact - row0; if (nrow > 64) nrow = 64;

    // load A (gathered rows): 1024 float4, 8 per thread
#pragma unroll
    for (int it = 0; it < 8; it++) {
        int e = tid + it * 128;
        int m = e >> 4, k4 = (e & 15) * 4;
        float4 v = make_float4(0.f, 0.f, 0.f, 0.f);
        if (m < nrow) {
            int gr = g_order[row0 + m];
            v = *(const float4*)&A[gr * 64 + k4];
        }
        As[m * 65 + k4] = v.x; As[m * 65 + k4 + 1] = v.y;
        As[m * 65 + k4 + 2] = v.z; As[m * 65 + k4 + 3] = v.w;
    }
    // load B: 2048 float4, 16 per thread
#pragma unroll
    for (int it = 0; it < 16; it++) {
        int e = tid + it * 128;
        int k = e >> 5, c4 = (e & 31) * 4;
        *(float4*)&Bs[k * 128 + c4] = *(const float4*)&W[k * 512 + colB + c4];
    }
    __syncthreads();

    int rowg = tid >> 4;          // 0..7: rows rowg*8 .. +7
    int cg = (tid & 15) * 2;      // col pair base within 32-chunk

    unsigned long long acc[8][4];
#pragma unroll
    for (int i = 0; i < 8; i++)
#pragma unroll
        for (int p = 0; p < 4; p++) acc[i][p] = 0ull;

#pragma unroll 8
    for (int k = 0; k < 64; k++) {
        unsigned long long b0 = *(const unsigned long long*)&Bs[k * 128 + cg];
        unsigned long long b1 = *(const unsigned long long*)&Bs[k * 128 + cg + 32];
        unsigned long long b2 = *(const unsigned long long*)&Bs[k * 128 + cg + 64];
        unsigned long long b3 = *(const unsigned long long*)&Bs[k * 128 + cg + 96];
#pragma unroll
        for (int i = 0; i < 8; i++) {
            float a = As[(rowg * 8 + i) * 65 + k];
            unsigned long long aa;
            asm("mov.b64 %0, {%1, %1};" : "=l"(aa) : "r"(__float_as_uint(a)));
            asm("fma.rn.f32x2 %0, %1, %2, %0;" : "+l"(acc[i][0]) : "l"(aa), "l"(b0));
            asm("fma.rn.f32x2 %0, %1, %2, %0;" : "+l"(acc[i][1]) : "l"(aa), "l"(b1));
            asm("fma.rn.f32x2 %0, %1, %2, %0;" : "+l"(acc[i][2]) : "l"(aa), "l"(b2));
            asm("fma.rn.f32x2 %0, %1, %2, %0;" : "+l"(acc[i][3]) : "l"(aa), "l"(b3));
        }
    }

#pragma unroll
    for (int i = 0; i < 8; i++) {
        int r = row0 + rowg * 8 + i;
        if (r >= nact) continue;
        int gr = g_order[r];
#pragma unroll
        for (int p = 0; p < 4; p++) {
            unsigned int u0, u1;
            asm("mov.b64 {%0, %1}, %2;" : "=r"(u0), "=r"(u1) : "l"(acc[i][p]));
            float2 v;
            v.x = __uint_as_float(u0); v.y = __uint_as_float(u1);
            int c = colB + cg + p * 32;
            if (addend_is_bias) {
                v.x += g_biasC[c]; v.y += g_biasC[c + 1];
            } else {
                const float2 b = *(const float2*)&addend[(size_t)gr * XD + c];
                v.x += b.x; v.y += b.y;
            }
            *(float2*)&C[(size_t)gr * XD + c] = v;
        }
    }
}

// ---------------- edge kernel: one warp per (compacted) active dst ----------
__global__ void k_edge(const int* __restrict__ node_mask,
                       const float* __restrict__ att, int t) {
    int w = (blockIdx.x * blockDim.x + threadIdx.x) >> 5;
    int lane = threadIdx.x & 31;
    if (w >= g_nact[t]) return;
    int n = g_order[w];

    int j0 = lane * 8;
    const float4 at0 = *(const float4*)&att[j0];
    const float4 at1 = *(const float4*)&att[j0 + 4];
    const float* xrp = &g_xlr[(size_t)n * XD + 256 + j0];
    const float4 xr0 = *(const float4*)xrp;
    const float4 xr1 = *(const float4*)(xrp + 4);

    float acc[8];
#pragma unroll
    for (int i = 0; i < 8; i++) acc[i] = 0.f;
    float den = 0.f;

    int beg = (n == 0) ? 0 : g_cnt[n - 1];
    int end = g_cnt[n];
    for (int e = beg; e < end; e++) {
        int s = g_srcs[e];
        if (node_mask[s] <= t) continue;
        const float* xp = &g_xlr[(size_t)s * XD + j0];
        const float4 x0 = *(const float4*)xp;
        const float4 x1 = *(const float4*)(xp + 4);
        float p, v;
        v = x0.x + xr0.x; v = v > 0.f ? v : 0.2f * v; p  = v * at0.x;
        v = x0.y + xr0.y; v = v > 0.f ? v : 0.2f * v; p += v * at0.y;
        v = x0.z + xr0.z; v = v > 0.f ? v : 0.2f * v; p += v * at0.z;
        v = x0.w + xr0.w; v = v > 0.f ? v : 0.2f * v; p += v * at0.w;
        v = x1.x + xr1.x; v = v > 0.f ? v : 0.2f * v; p += v * at1.x;
        v = x1.y + xr1.y; v = v > 0.f ? v : 0.2f * v; p += v * at1.y;
        v = x1.z + xr1.z; v = v > 0.f ? v : 0.2f * v; p += v * at1.z;
        v = x1.w + xr1.w; v = v > 0.f ? v : 0.2f * v; p += v * at1.w;
        p += __shfl_xor_sync(0xffffffffu, p, 1);
        p += __shfl_xor_sync(0xffffffffu, p, 2);
        p += __shfl_xor_sync(0xffffffffu, p, 4);
        float ex = __expf(p);   // softmax is shift-invariant; scores O(1)
        den += ex;
        acc[0] += ex * x0.x; acc[1] += ex * x0.y;
        acc[2] += ex * x0.z; acc[3] += ex * x0.w;
        acc[4] += ex * x1.x; acc[5] += ex * x1.y;
        acc[6] += ex * x1.z; acc[7] += ex * x1.w;
    }

    float rden = 1.f / fmaxf(den, 1e-16f);
    float vres[8];
#pragma unroll
    for (int i = 0; i < 8; i++) {
        float v = acc[i] * rden;
        v += __shfl_xor_sync(0xffffffffu, v, 8);   // sum heads
        v += __shfl_xor_sync(0xffffffffu, v, 16);
        vres[i] = v;
    }
    if (lane < 8) {
#pragma unroll
        for (int i = 0; i < 8; i++) {
            int c = lane * 8 + i;
            g_h[n * 64 + c] = tanhf(vres[i] + g_bias2[c]);
        }
    }
}

// ---------------- out = (h @ Wg + bg) * (current_state > 0) -----------------
__global__ void k_out(const float* __restrict__ Wg, const float* __restrict__ bg,
                      const int* __restrict__ cs, float* __restrict__ out) {
    __shared__ float Ws[64 * 32];
    __shared__ float hs[8][64];
    int tid = threadIdx.x;
    for (int i = tid; i < 64 * 32; i += 256) Ws[i] = Wg[i];
    for (int i = tid; i < 8 * 64; i += 256) {
        int r = blockIdx.x * 8 + (i >> 6);
        hs[i >> 6][i & 63] = (r < N_NODES) ? g_h[r * 64 + (i & 63)] : 0.f;
    }
    __syncthreads();
    int ty = tid >> 5;
    int c = tid & 31;
    int r = blockIdx.x * 8 + ty;
    if (r >= N_NODES) return;
    float s = bg[c];
#pragma unroll
    for (int k = 0; k < 64; k++) s += hs[ty][k] * Ws[k * 32 + c];
    out[r * 32 + c] = (cs[r] > 0) ? s : 0.f;
}

// ---------------- launch -----------------------------------------------------
extern "C" void kernel_launch(void* const* d_in, const int* in_sizes, int n_in,
                              void* d_out, int out_size) {
    const float* feat  = (const float*)d_in[0];
    const float* W_in  = (const float*)d_in[1];
    const float* b_in  = (const float*)d_in[2];
    const float* Wl    = (const float*)d_in[3];
    const float* bl    = (const float*)d_in[4];
    const float* Wr    = (const float*)d_in[5];
    const float* br    = (const float*)d_in[6];
    const float* att   = (const float*)d_in[7];
    const float* bconv = (const float*)d_in[8];
    const float* Wg    = (const float*)d_in[9];
    const float* bg    = (const float*)d_in[10];
    const int*   ei    = (const int*)d_in[11];
    const int*   mask  = (const int*)d_in[12];
    const int*   cstat = (const int*)d_in[13];
    float* out = (float*)d_out;

    float *p_h0, *p_h, *p_base, *p_xlr, *p_Wc1, *p_Wc2;
    cudaGetSymbolAddress((void**)&p_h0, g_h0);
    cudaGetSymbolAddress((void**)&p_h, g_h);
    cudaGetSymbolAddress((void**)&p_base, g_base);
    cudaGetSymbolAddress((void**)&p_xlr, g_xlr);
    cudaGetSymbolAddress((void**)&p_Wc1, g_Wc1);
    cudaGetSymbolAddress((void**)&p_Wc2, g_Wc2);

    static const int GEMM_SMEM = (64 * 65 + 64 * 128) * 4;  // 49408 B
    cudaFuncSetAttribute(k_gemm, cudaFuncAttributeMaxDynamicSharedMemorySize, GEMM_SMEM);

    k_zero<<<(N_NODES + 255) / 256, 256>>>();
    k_hist<<<(N_NODES + 255) / 256, 256>>>(mask);
    k_count<<<(E_EDGES + 255) / 256, 256>>>(ei);
    k_prepw<<<(HID * XD + 255) / 256, 256>>>(Wl, Wr, bl, br, bconv);
    k_h0<<<(N_NODES + 3) / 4, 256>>>(feat, W_in, b_in);
    k_scan<<<1, 1024>>>();
    k_scatter<<<(N_NODES + 255) / 256, 256>>>(mask);
    k_fill<<<(E_EDGES + 255) / 256, 256>>>(ei);

    dim3 gg((N_NODES + 63) / 64, XD / 128);
    // base = h0 @ Wc2 + [bl|br]  (rows active at t=0 only; superset of later)
    k_gemm<<<gg, 128, GEMM_SMEM>>>(p_h0, p_Wc2, nullptr, 1, 0, p_base);

    for (int t = 0; t < T_STEPS; t++) {
        k_gemm<<<gg, 128, GEMM_SMEM>>>(p_h, p_Wc1, p_base, 0, t, p_xlr);
        k_edge<<<(N_NODES * 32 + 255) / 256, 256>>>(mask, att, t);
    }

    k_out<<<(N_NODES + 7) / 8, 256>>>(Wg, bg, cstat, out);
}

// round 5
// speedup vs baseline: 2.6942x; 1.2606x over previous
#include <cuda_runtime.h>
#include <math.h>
#include <stdint.h>

#define N_NODES 50000
#define E_EDGES 200000
#define TOT_E   250000
#define HID     64
#define XD      512
#define T_STEPS 3
#define PAD     132   // smem row pitch (words) for conflict-free frag loads

// ---------------- device scratch --------------------------------------------
__device__ int   g_cnt[N_NODES + 1];
__device__ int   g_cur[N_NODES];
__device__ int   g_srcs[TOT_E];       // CSR entries as COMPACT src indices
__device__ int   g_order[N_NODES];    // compact slot -> node id (mask desc)
__device__ int   g_inv[N_NODES];      // node id -> compact slot
__device__ int   g_hist[4];
__device__ int   g_bcur[4];
__device__ int   g_nact[4];
__device__ float g_h0[N_NODES * HID];
__device__ float g_h[N_NODES * HID];
__device__ float g_xlr[(size_t)(N_NODES + 128) * XD];   // compact-indexed
__device__ float g_Wp[128 * XD];      // W' = rows of [Wl|Wr], tf32-truncated
__device__ float g_biasC[XD];
__device__ float g_bias2[HID];

// ---------------- prep ------------------------------------------------------
__global__ void k_zero() {
    int i = blockIdx.x * blockDim.x + threadIdx.x;
    if (i < N_NODES) g_cnt[i] = 1;
    if (i < 4) { g_hist[i] = 0; g_bcur[i] = 0; }
}

__global__ void k_hist(const int* __restrict__ mask) {
    __shared__ int sh[4];
    if (threadIdx.x < 4) sh[threadIdx.x] = 0;
    __syncthreads();
    int i = blockIdx.x * blockDim.x + threadIdx.x;
    if (i < N_NODES) {
        int m = mask[i]; m = m < 0 ? 0 : (m > 3 ? 3 : m);
        atomicAdd(&sh[m], 1);
    }
    __syncthreads();
    if (threadIdx.x < 4) atomicAdd(&g_hist[threadIdx.x], sh[threadIdx.x]);
}

__global__ void k_count(const int* __restrict__ ei) {
    int e = blockIdx.x * blockDim.x + threadIdx.x;
    if (e < E_EDGES) atomicAdd(&g_cnt[ei[E_EDGES + e]], 1);
}

__global__ void k_scan() {
    __shared__ int wsum[32];
    int tid = threadIdx.x, lane = tid & 31, wid = tid >> 5;
    int carry = 0;
    for (int base = 0; base < N_NODES; base += 1024) {
        int i = base + tid;
        int v = (i < N_NODES) ? g_cnt[i] : 0;
        int sv = v;
#pragma unroll
        for (int d = 1; d < 32; d <<= 1) {
            int u = __shfl_up_sync(0xffffffffu, sv, d);
            if (lane >= d) sv += u;
        }
        if (lane == 31) wsum[wid] = sv;
        __syncthreads();
        if (wid == 0) {
            int w = wsum[lane];
#pragma unroll
            for (int d = 1; d < 32; d <<= 1) {
                int u = __shfl_up_sync(0xffffffffu, w, d);
                if (lane >= d) w += u;
            }
            wsum[lane] = w;
        }
        __syncthreads();
        int add = (wid > 0) ? wsum[wid - 1] : 0;
        if (i < N_NODES) g_cnt[i] = sv + add + carry;
        int total = wsum[31];
        __syncthreads();
        carry += total;
    }
}

__global__ void k_scatter(const int* __restrict__ mask) {
    __shared__ int scnt[4], sbase[4];
    int tid = threadIdx.x;
    if (tid < 4) scnt[tid] = 0;
    __syncthreads();
    int i = blockIdx.x * blockDim.x + tid;
    int m = 0, loc = 0;
    if (i < N_NODES) {
        m = mask[i]; m = m < 0 ? 0 : (m > 3 ? 3 : m);
        loc = atomicAdd(&scnt[m], 1);
    }
    __syncthreads();
    if (tid < 4) sbase[tid] = atomicAdd(&g_bcur[tid], scnt[tid]);
    __syncthreads();
    if (i < N_NODES) {
        int h1 = g_hist[1], h2 = g_hist[2], h3 = g_hist[3];
        int start = (m == 3) ? 0 : ((m == 2) ? h3 : ((m == 1) ? h3 + h2 : h3 + h2 + h1));
        int pos = start + sbase[m] + loc;
        g_order[pos] = i;
        g_inv[i] = pos;
        int beg = (i == 0) ? 0 : g_cnt[i - 1];
        g_srcs[beg] = pos;       // self loop, already compact
        g_cur[i] = beg + 1;
        if (i == 0) {
            g_nact[0] = h1 + h2 + h3;
            g_nact[1] = h2 + h3;
            g_nact[2] = h3;
            g_nact[3] = 0;
        }
    }
}

__global__ void k_fill(const int* __restrict__ ei) {
    int e = blockIdx.x * blockDim.x + threadIdx.x;
    if (e >= E_EDGES) return;
    int d = ei[E_EDGES + e];
    int p = atomicAdd(&g_cur[d], 1);
    g_srcs[p] = g_inv[ei[e]];
}

// ---------------- weight prep: W'[k][j], tf32-truncated ----------------------
__global__ void k_prepb(const float* __restrict__ Wl, const float* __restrict__ Wr,
                        const float* __restrict__ bl, const float* __restrict__ br,
                        const float* __restrict__ bconv) {
    int idx = blockIdx.x * blockDim.x + threadIdx.x;   // 65536
    if (idx < 128 * XD) {
        int k = idx >> 9, j = idx & 511;
        float v = (j < 256) ? Wl[k * 256 + j] : Wr[k * 256 + (j - 256)];
        uint32_t tv;
        asm("cvt.rna.tf32.f32 %0, %1;" : "=r"(tv) : "f"(v));
        g_Wp[idx] = __uint_as_float(tv);
    }
    if (idx < XD) g_biasC[idx] = (idx < 256) ? bl[idx] : br[idx - 256];
    if (idx < HID) g_bias2[idx] = bconv[idx] + bconv[64 + idx] + bconv[128 + idx] + bconv[192 + idx];
}

// ---------------- h0 = feat @ W_in + b_in -----------------------------------
__global__ void k_h0(const float* __restrict__ feat, const float* __restrict__ W_in,
                     const float* __restrict__ b_in) {
    __shared__ float Ws[32 * 64];
    __shared__ float fs[4][32];
    int tid = threadIdx.x;
    for (int i = tid; i < 32 * 64; i += 256) Ws[i] = W_in[i];
    if (tid < 128) {
        int r = blockIdx.x * 4 + (tid >> 5);
        fs[tid >> 5][tid & 31] = (r < N_NODES) ? feat[r * 32 + (tid & 31)] : 0.f;
    }
    __syncthreads();
    int ty = tid >> 6;
    int c = tid & 63;
    int r = blockIdx.x * 4 + ty;
    if (r >= N_NODES) return;
    float s = b_in[c];
#pragma unroll
    for (int k = 0; k < 32; k++) s += fs[ty][k] * Ws[k * 64 + c];
    g_h0[r * 64 + c] = s;
    g_h[r * 64 + c] = s;
}

// ---------------- HMMA tf32 GEMM: xlr[compact,512] = [h|h0] @ W' + biasC ----
// grid (4 colblocks, 37); block 256 = 8 warps (2M x 4N); tile 128x128, K=128.
#define GEMM_SMEM (2 * 128 * PAD * 4)

__global__ __launch_bounds__(256, 1) void k_gemm_mma(int tsel) {
    extern __shared__ uint32_t sm[];
    uint32_t* As = sm;               // [128][PAD]
    uint32_t* Bs = sm + 128 * PAD;   // [128][PAD]
    int nact = g_nact[tsel];
    int ntile = (nact + 127) >> 7;
    int colB = blockIdx.x * 128;
    int tid = threadIdx.x, wid = tid >> 5, lane = tid & 31;
    int mwarp = wid >> 2, nwarp = wid & 3;
    int group = lane >> 2, tig = lane & 3;

    // ---- B tile once per CTA: Bs[k][c] = W'[k][colB+c] ---------------------
    for (int i = tid; i < 128 * 32; i += 256) {
        int k = i >> 5, c4 = (i & 31) * 4;
        float4 v = *(const float4*)&g_Wp[k * 512 + colB + c4];
        uint32_t* d = &Bs[k * PAD + c4];
        d[0] = __float_as_uint(v.x); d[1] = __float_as_uint(v.y);
        d[2] = __float_as_uint(v.z); d[3] = __float_as_uint(v.w);
    }

    // bias registers: cols colB + nwarp*32 + nf*8 + 2*tig
    float2 bia[4];
#pragma unroll
    for (int nf = 0; nf < 4; nf++)
        bia[nf] = *(const float2*)&g_biasC[colB + nwarp * 32 + nf * 8 + 2 * tig];

    // per-thread fragment base pointers
    const uint32_t* aBase = &As[(mwarp * 64 + group) * PAD + tig];
    const uint32_t* bBase = &Bs[tig * PAD + nwarp * 32 + group];

    for (int tile = blockIdx.y; tile < ntile; tile += gridDim.y) {
        int row0 = tile << 7;
        __syncthreads();   // all warps done with previous As
        // ---- A tile: row m = [h[gr] | h0[gr]], tf32-truncated --------------
        {
            int m = tid >> 1, which = tid & 1;
            int r = row0 + m;
            bool valid = (r < nact);
            int gr = valid ? g_order[r] : 0;
            const float* srcA = which ? g_h0 : g_h;
            const float4* rowp = (const float4*)&srcA[(size_t)gr * 64];
            uint32_t* dst = &As[m * PAD + which * 64];
#pragma unroll
            for (int i = 0; i < 16; i++) {
                float4 v = valid ? rowp[i] : make_float4(0.f, 0.f, 0.f, 0.f);
                uint32_t t0, t1, t2, t3;
                asm("cvt.rna.tf32.f32 %0, %1;" : "=r"(t0) : "f"(v.x));
                asm("cvt.rna.tf32.f32 %0, %1;" : "=r"(t1) : "f"(v.y));
                asm("cvt.rna.tf32.f32 %0, %1;" : "=r"(t2) : "f"(v.z));
                asm("cvt.rna.tf32.f32 %0, %1;" : "=r"(t3) : "f"(v.w));
                dst[i * 4] = t0; dst[i * 4 + 1] = t1;
                dst[i * 4 + 2] = t2; dst[i * 4 + 3] = t3;
            }
        }
        __syncthreads();

        float acc[4][4][4];
#pragma unroll
        for (int mf = 0; mf < 4; mf++)
#pragma unroll
            for (int nf = 0; nf < 4; nf++)
#pragma unroll
                for (int q = 0; q < 4; q++) acc[mf][nf][q] = 0.f;

#pragma unroll 4
        for (int k0 = 0; k0 < 16; k0++) {
            uint32_t a[4][4], b[4][2];
#pragma unroll
            for (int mf = 0; mf < 4; mf++) {
                const uint32_t* ap = aBase + mf * 16 * PAD + k0 * 8;
                a[mf][0] = ap[0];
                a[mf][1] = ap[8 * PAD];
                a[mf][2] = ap[4];
                a[mf][3] = ap[8 * PAD + 4];
            }
#pragma unroll
            for (int nf = 0; nf < 4; nf++) {
                const uint32_t* bp = bBase + k0 * 8 * PAD + nf * 8;
                b[nf][0] = bp[0];
                b[nf][1] = bp[4 * PAD];
            }
#pragma unroll
            for (int mf = 0; mf < 4; mf++)
#pragma unroll
                for (int nf = 0; nf < 4; nf++) {
                    asm volatile(
                        "mma.sync.aligned.m16n8k8.row.col.f32.tf32.tf32.f32 "
                        "{%0,%1,%2,%3}, {%4,%5,%6,%7}, {%8,%9}, {%0,%1,%2,%3};"
                        : "+f"(acc[mf][nf][0]), "+f"(acc[mf][nf][1]),
                          "+f"(acc[mf][nf][2]), "+f"(acc[mf][nf][3])
                        : "r"(a[mf][0]), "r"(a[mf][1]), "r"(a[mf][2]), "r"(a[mf][3]),
                          "r"(b[nf][0]), "r"(b[nf][1]));
                }
        }

        // ---- epilogue: bias + direct stores (compact rows) -----------------
#pragma unroll
        for (int mf = 0; mf < 4; mf++) {
            int r0 = row0 + mwarp * 64 + mf * 16 + group;
#pragma unroll
            for (int nf = 0; nf < 4; nf++) {
                int c = colB + nwarp * 32 + nf * 8 + 2 * tig;
                if (r0 < nact) {
                    float2 v = make_float2(acc[mf][nf][0] + bia[nf].x,
                                           acc[mf][nf][1] + bia[nf].y);
                    *(float2*)&g_xlr[(size_t)r0 * XD + c] = v;
                }
                if (r0 + 8 < nact) {
                    float2 v = make_float2(acc[mf][nf][2] + bia[nf].x,
                                           acc[mf][nf][3] + bia[nf].y);
                    *(float2*)&g_xlr[(size_t)(r0 + 8) * XD + c] = v;
                }
            }
        }
    }
}

// ---------------- edge kernel: one warp per compact active dst ---------------
__global__ void k_edge(const float* __restrict__ att, int t) {
    int w = (blockIdx.x * blockDim.x + threadIdx.x) >> 5;
    int lane = threadIdx.x & 31;
    int na = g_nact[t];
    if (w >= na) return;
    int norig = g_order[w];

    int j0 = lane * 8;
    const float4 at0 = *(const float4*)&att[j0];
    const float4 at1 = *(const float4*)&att[j0 + 4];
    const float* xrp = &g_xlr[(size_t)w * XD + 256 + j0];
    const float4 xr0 = *(const float4*)xrp;
    const float4 xr1 = *(const float4*)(xrp + 4);

    float acc[8];
#pragma unroll
    for (int i = 0; i < 8; i++) acc[i] = 0.f;
    float den = 0.f;

    int beg = (norig == 0) ? 0 : g_cnt[norig - 1];
    int end = g_cnt[norig];
    for (int e = beg; e < end; e++) {
        int cs = g_srcs[e];
        if (cs >= na) continue;            // src inactive at step t
        const float* xp = &g_xlr[(size_t)cs * XD + j0];
        const float4 x0 = *(const float4*)xp;
        const float4 x1 = *(const float4*)(xp + 4);
        float p, v;
        v = x0.x + xr0.x; v = v > 0.f ? v : 0.2f * v; p  = v * at0.x;
        v = x0.y + xr0.y; v = v > 0.f ? v : 0.2f * v; p += v * at0.y;
        v = x0.z + xr0.z; v = v > 0.f ? v : 0.2f * v; p += v * at0.z;
        v = x0.w + xr0.w; v = v > 0.f ? v : 0.2f * v; p += v * at0.w;
        v = x1.x + xr1.x; v = v > 0.f ? v : 0.2f * v; p += v * at1.x;
        v = x1.y + xr1.y; v = v > 0.f ? v : 0.2f * v; p += v * at1.y;
        v = x1.z + xr1.z; v = v > 0.f ? v : 0.2f * v; p += v * at1.z;
        v = x1.w + xr1.w; v = v > 0.f ? v : 0.2f * v; p += v * at1.w;
        p += __shfl_xor_sync(0xffffffffu, p, 1);
        p += __shfl_xor_sync(0xffffffffu, p, 2);
        p += __shfl_xor_sync(0xffffffffu, p, 4);
        float ex = __expf(p);              // softmax shift-invariant
        den += ex;
        acc[0] += ex * x0.x; acc[1] += ex * x0.y;
        acc[2] += ex * x0.z; acc[3] += ex * x0.w;
        acc[4] += ex * x1.x; acc[5] += ex * x1.y;
        acc[6] += ex * x1.z; acc[7] += ex * x1.w;
    }

    float rden = 1.f / fmaxf(den, 1e-16f);
    float vres[8];
#pragma unroll
    for (int i = 0; i < 8; i++) {
        float v = acc[i] * rden;
        v += __shfl_xor_sync(0xffffffffu, v, 8);
        v += __shfl_xor_sync(0xffffffffu, v, 16);
        vres[i] = v;
    }
    if (lane < 8) {
#pragma unroll
        for (int i = 0; i < 8; i++) {
            int c = lane * 8 + i;
            g_h[norig * 64 + c] = tanhf(vres[i] + g_bias2[c]);
        }
    }
}

// ---------------- out = (h @ Wg + bg) * (current_state > 0) -----------------
__global__ void k_out(const float* __restrict__ Wg, const float* __restrict__ bg,
                      const int* __restrict__ cs, float* __restrict__ out) {
    __shared__ float Ws[64 * 32];
    __shared__ float hs[8][64];
    int tid = threadIdx.x;
    for (int i = tid; i < 64 * 32; i += 256) Ws[i] = Wg[i];
    for (int i = tid; i < 8 * 64; i += 256) {
        int r = blockIdx.x * 8 + (i >> 6);
        hs[i >> 6][i & 63] = (r < N_NODES) ? g_h[r * 64 + (i & 63)] : 0.f;
    }
    __syncthreads();
    int ty = tid >> 5;
    int c = tid & 31;
    int r = blockIdx.x * 8 + ty;
    if (r >= N_NODES) return;
    float s = bg[c];
#pragma unroll
    for (int k = 0; k < 64; k++) s += hs[ty][k] * Ws[k * 32 + c];
    out[r * 32 + c] = (cs[r] > 0) ? s : 0.f;
}

// ---------------- launch -----------------------------------------------------
extern "C" void kernel_launch(void* const* d_in, const int* in_sizes, int n_in,
                              void* d_out, int out_size) {
    const float* feat  = (const float*)d_in[0];
    const float* W_in  = (const float*)d_in[1];
    const float* b_in  = (const float*)d_in[2];
    const float* Wl    = (const float*)d_in[3];
    const float* bl    = (const float*)d_in[4];
    const float* Wr    = (const float*)d_in[5];
    const float* br    = (const float*)d_in[6];
    const float* att   = (const float*)d_in[7];
    const float* bconv = (const float*)d_in[8];
    const float* Wg    = (const float*)d_in[9];
    const float* bg    = (const float*)d_in[10];
    const int*   ei    = (const int*)d_in[11];
    const int*   mask  = (const int*)d_in[12];
    const int*   cstat = (const int*)d_in[13];
    float* out = (float*)d_out;

    cudaFuncSetAttribute(k_gemm_mma, cudaFuncAttributeMaxDynamicSharedMemorySize, GEMM_SMEM);

    k_zero<<<(N_NODES + 255) / 256, 256>>>();
    k_hist<<<(N_NODES + 255) / 256, 256>>>(mask);
    k_count<<<(E_EDGES + 255) / 256, 256>>>(ei);
    k_prepb<<<256, 256>>>(Wl, Wr, bl, br, bconv);
    k_h0<<<(N_NODES + 3) / 4, 256>>>(feat, W_in, b_in);
    k_scan<<<1, 1024>>>();
    k_scatter<<<(N_NODES + 255) / 256, 256>>>(mask);
    k_fill<<<(E_EDGES + 255) / 256, 256>>>(ei);

    for (int t = 0; t < T_STEPS; t++) {
        k_gemm_mma<<<dim3(4, 37), 256, GEMM_SMEM>>>(t);
        k_edge<<<(N_NODES * 32 + 255) / 256, 256>>>(att, t);
    }

    k_out<<<(N_NODES + 7) / 8, 256>>>(Wg, bg, cstat, out);
}